// round 11
// baseline (speedup 1.0000x reference)
#include <cuda_runtime.h>

// Problem constants
#define BB   4
#define NPTS 16384
#define MPTS 4096
#define CCH  256

typedef unsigned long long ull;

// Scratch (device globals; no allocation allowed)
__device__ float g_zT[(size_t)BB * MPTS * CCH];   // [b][m][o]
__device__ float g_y1[(size_t)BB * CCH * NPTS];   // [b][o][n]
__device__ float g_w [(size_t)BB * NPTS * 4];
__device__ int   g_idx[(size_t)BB * NPTS * 4];
__device__ float g_WT1a[CCH * CCH];               // W1[:,0:C]   transposed -> [k][o]
__device__ float g_WT1b[CCH * CCH];               // W1[:,C:2C]  transposed -> [k][o]
__device__ float g_WT2 [CCH * CCH];               // W2          transposed -> [k][o]

__device__ __forceinline__ void cp_async16(void* smem_dst, const void* gmem_src) {
    unsigned s = (unsigned)__cvta_generic_to_shared(smem_dst);
    asm volatile("cp.async.cg.shared.global [%0], [%1], 16;\n" :: "r"(s), "l"(gmem_src));
}
#define CP_COMMIT() asm volatile("cp.async.commit_group;\n" ::: "memory")
#define CP_WAIT0()  asm volatile("cp.async.wait_group 0;\n" ::: "memory")

// ---- packed f32x2 helpers ----
__device__ __forceinline__ void ffma2(ull& c, ull a, ull b) {
    asm("fma.rn.f32x2 %0, %1, %2, %0;" : "+l"(c) : "l"(a), "l"(b));
}
__device__ __forceinline__ ull fma2v(ull a, ull b, ull c) {
    ull r; asm("fma.rn.f32x2 %0, %1, %2, %3;" : "=l"(r) : "l"(a), "l"(b), "l"(c)); return r;
}
__device__ __forceinline__ ull pack2(float lo, float hi) {
    ull r;
    asm("mov.b64 %0, {%1, %2};" : "=l"(r) : "f"(lo), "f"(hi));
    return r;
}
__device__ __forceinline__ float2 unpack2(ull v) {
    float lo, hi;
    asm("mov.b64 {%0, %1}, %2;" : "=f"(lo), "=f"(hi) : "l"(v));
    return make_float2(lo, hi);
}
__device__ __forceinline__ void lds_v2u64(ull& a, ull& b, unsigned addr) {
    asm volatile("ld.shared.v2.u64 {%0, %1}, [%2];" : "=l"(a), "=l"(b) : "r"(addr));
}

extern __shared__ float sm_f[];

// ---------------------------------------------------------------------------
// Weight transpose (runs once per launch, trivial cost).
// ---------------------------------------------------------------------------
__global__ void __launch_bounds__(256) transpose_w_kernel(
    const float* __restrict__ W1, const float* __restrict__ W2)
{
    int k = blockIdx.x;
    int o = threadIdx.x;
    g_WT1a[k * CCH + o] = W1[(size_t)o * (2 * CCH) + k];
    g_WT1b[k * CCH + o] = W1[(size_t)o * (2 * CCH) + CCH + k];
    g_WT2 [k * CCH + o] = W2[(size_t)o * CCH + k];
}

// ---------------------------------------------------------------------------
// kNN. Selection must be bit-exact vs the XLA reference.
// Fast gate (approx, fma-contracted f32x2):  e = dot - s2/2 compared against
//   t = 0.5*(s1 - d2) - 1e-3  (equiv. d < d2 + 2e-3; contraction error
//   <= ~1e-5 << margin, so the gate can never miss a true insert).
// smem pair-interleaved: per candidate pair [x0,x1,y0,y1,z0,z1,nh0,nh1],
// nh = -s2/2 (exact scale); exact path recovers s2 = nh * -2 (exact).
// On gate hit: VERIFIED bit-exact scalar __f*_rn recompute + insert chain.
// Each thread processes 2 queries (tid and tid+256) to amortize the loads.
// ---------------------------------------------------------------------------
struct Top3 { float d0, d1, d2; int i0, i1, i2; float t, s1; };

__device__ __forceinline__ void exact_insert4(Top3& s, int m,
                                              const float* sm, float px, float py, float pz)
{
#pragma unroll
    for (int u = 0; u < 4; ++u) {
        int idx = m + u;
        int base = (idx >> 1) * 8 + (idx & 1);
        float x  = sm[base + 0];
        float y  = sm[base + 2];
        float z  = sm[base + 4];
        float nh = sm[base + 6];
        float s2 = __fmul_rn(nh, -2.0f);                     // exact
        float dot = __fadd_rn(__fadd_rn(__fmul_rn(px, x),
                                        __fmul_rn(py, y)),
                              __fmul_rn(pz, z));
        float d = __fadd_rn(s.s1, s2);
        d = __fsub_rn(d, __fmul_rn(2.0f, dot));
        d = fmaxf(d, 0.0f);
        if (d < s.d2) {
            if (d < s.d1) {
                if (d < s.d0) { s.d2 = s.d1; s.i2 = s.i1; s.d1 = s.d0; s.i1 = s.i0; s.d0 = d; s.i0 = idx; }
                else          { s.d2 = s.d1; s.i2 = s.i1; s.d1 = d;  s.i1 = idx; }
            } else            { s.d2 = d;  s.i2 = idx; }
        }
    }
    s.t = 0.5f * (s.s1 - s.d2) - 1e-3f;   // gate threshold (approx-side only)
}

__device__ __forceinline__ void knn_store(const Top3& s, int b, int n)
{
    float r0 = __fdiv_rn(1.0f, __fadd_rn(s.d0, 1e-8f));
    float r1 = __fdiv_rn(1.0f, __fadd_rn(s.d1, 1e-8f));
    float r2 = __fdiv_rn(1.0f, __fadd_rn(s.d2, 1e-8f));
    float sum = __fadd_rn(__fadd_rn(r0, r1), r2);
    size_t base = ((size_t)b * NPTS + n) * 4;
    g_w[base + 0] = __fdiv_rn(r0, sum);
    g_w[base + 1] = __fdiv_rn(r1, sum);
    g_w[base + 2] = __fdiv_rn(r2, sum);
    g_w[base + 3] = 0.f;
    g_idx[base + 0] = s.i0; g_idx[base + 1] = s.i1; g_idx[base + 2] = s.i2; g_idx[base + 3] = 0;
}

__device__ __forceinline__ void knn_body(const float* __restrict__ p1,
                                         const float* __restrict__ p2,
                                         int tile, int b)
{
    // fill pair-interleaved smem
    const float* P2 = p2 + (size_t)b * MPTS * 3;
    for (int i = threadIdx.x; i < MPTS; i += 256) {
        float x = P2[i * 3 + 0];
        float y = P2[i * 3 + 1];
        float z = P2[i * 3 + 2];
        float s2 = __fadd_rn(__fadd_rn(__fmul_rn(x, x), __fmul_rn(y, y)),
                             __fmul_rn(z, z));
        int base = (i >> 1) * 8 + (i & 1);
        sm_f[base + 0] = x;
        sm_f[base + 2] = y;
        sm_f[base + 4] = z;
        sm_f[base + 6] = __fmul_rn(s2, -0.5f);               // exact
    }
    __syncthreads();

    unsigned sbase = (unsigned)__cvta_generic_to_shared(sm_f);

    // two queries per thread
    int n0 = tile * 512 + threadIdx.x;
    int n1 = n0 + 256;
    const float* qa = p1 + ((size_t)b * NPTS + n0) * 3;
    const float* qb = p1 + ((size_t)b * NPTS + n1) * 3;
    float ax = qa[0], ay = qa[1], az = qa[2];
    float bx = qb[0], by = qb[1], bz = qb[2];

    Top3 A, B;
    A.d0 = A.d1 = A.d2 = 3.4e38f; A.i0 = A.i1 = A.i2 = 0;
    B.d0 = B.d1 = B.d2 = 3.4e38f; B.i0 = B.i1 = B.i2 = 0;
    A.s1 = __fadd_rn(__fadd_rn(__fmul_rn(ax, ax), __fmul_rn(ay, ay)), __fmul_rn(az, az));
    B.s1 = __fadd_rn(__fadd_rn(__fmul_rn(bx, bx), __fmul_rn(by, by)), __fmul_rn(bz, bz));
    A.t = -3.4e38f;
    B.t = -3.4e38f;

    ull ax2 = pack2(ax, ax), ay2 = pack2(ay, ay), az2 = pack2(az, az);
    ull bx2 = pack2(bx, bx), by2 = pack2(by, by), bz2 = pack2(bz, bz);

    for (int m = 0; m < MPTS; m += 4) {
        unsigned addr = sbase + (m >> 1) * 32;
        ull xy0a, xy0b, znh0a, znh0b;            // pair 0: (x0,x1),(y0,y1),(z0,z1),(nh0,nh1)
        ull xy1a, xy1b, znh1a, znh1b;            // pair 1
        lds_v2u64(xy0a, xy0b, addr);
        lds_v2u64(znh0a, znh0b, addr + 16);
        lds_v2u64(xy1a, xy1b, addr + 32);
        lds_v2u64(znh1a, znh1b, addr + 48);

        // query A: e = px*x + py*y + pz*z + nh   (approx, contraction OK)
        ull eA0 = fma2v(ax2, xy0a, fma2v(ay2, xy0b, fma2v(az2, znh0a, znh0b)));
        ull eA1 = fma2v(ax2, xy1a, fma2v(ay2, xy1b, fma2v(az2, znh1a, znh1b)));
        float2 fA0 = unpack2(eA0), fA1 = unpack2(eA1);
        float eAm = fmaxf(fmaxf(fA0.x, fA0.y), fmaxf(fA1.x, fA1.y));
        if (eAm > A.t) exact_insert4(A, m, sm_f, ax, ay, az);

        // query B
        ull eB0 = fma2v(bx2, xy0a, fma2v(by2, xy0b, fma2v(bz2, znh0a, znh0b)));
        ull eB1 = fma2v(bx2, xy1a, fma2v(by2, xy1b, fma2v(bz2, znh1a, znh1b)));
        float2 fB0 = unpack2(eB0), fB1 = unpack2(eB1);
        float eBm = fmaxf(fmaxf(fB0.x, fB0.y), fmaxf(fB1.x, fB1.y));
        if (eBm > B.t) exact_insert4(B, m, sm_f, bx, by, bz);
    }

    knn_store(A, b, n0);
    knn_store(B, b, n1);
}

// ---------------------------------------------------------------------------
// SGEMM 128x128, kTile=32, double-buffered cp.async both operands.
// fma.rn.f32x2 inner loop; per-element accumulation order identical to the
// verified scalar kernel (per-lane rn rounding) -> bit-identical output.
// ---------------------------------------------------------------------------
template <int MODE>
__device__ __forceinline__ void gemm_body(
    const float* __restrict__ AT,          // [K][CCH] transposed weights
    const float* __restrict__ Bp, int ldb, int K,
    const float* __restrict__ bias,
    float* __restrict__ Op, int ldn,
    int n0, int o0, int b)
{
    float (*As)[32][128] = (float(*)[32][128])sm_f;                 // 32KB
    float (*Bs)[32][128] = (float(*)[32][128])(sm_f + 2 * 32 * 128);

    int tid = threadIdx.x;
    int tx = tid & 15;
    int ty = tid >> 4;

    int ck[4], cc[4];
#pragma unroll
    for (int i = 0; i < 4; ++i) {
        int f = tid + 256 * i;
        ck[i] = f >> 5;
        cc[i] = (f & 31) * 4;
    }

    ull acc2[4][8];
#pragma unroll
    for (int i = 0; i < 4; ++i)
#pragma unroll
        for (int j = 0; j < 8; ++j) acc2[i][j] = 0ull;

    // prologue: stage 0
#pragma unroll
    for (int i = 0; i < 4; ++i) {
        cp_async16(&As[0][ck[i]][cc[i]], AT + (size_t)ck[i] * CCH + o0 + cc[i]);
        cp_async16(&Bs[0][ck[i]][cc[i]], Bp + (size_t)ck[i] * ldb + n0 + cc[i]);
    }
    CP_COMMIT();
    CP_WAIT0();
    __syncthreads();

    int cur = 0;
    for (int k0 = 0; k0 < K; k0 += 32) {
        bool nxt = (k0 + 32) < K;
        if (nxt) {
            int nb = cur ^ 1;
#pragma unroll
            for (int i = 0; i < 4; ++i) {
                cp_async16(&As[nb][ck[i]][cc[i]],
                           AT + (size_t)(k0 + 32 + ck[i]) * CCH + o0 + cc[i]);
                cp_async16(&Bs[nb][ck[i]][cc[i]],
                           Bp + (size_t)(k0 + 32 + ck[i]) * ldb + n0 + cc[i]);
            }
            CP_COMMIT();
        }
#pragma unroll
        for (int kk = 0; kk < 32; ++kk) {
            ull aa[4];
            aa[0] = *(const ull*)&As[cur][kk][ty * 4];          // o pair (0,1)
            aa[1] = *(const ull*)&As[cur][kk][ty * 4 + 2];      // o pair (2,3)
            aa[2] = *(const ull*)&As[cur][kk][ty * 4 + 64];     // o pair (4,5)
            aa[3] = *(const ull*)&As[cur][kk][ty * 4 + 66];     // o pair (6,7)
            float4 y0 = *(const float4*)&Bs[cur][kk][tx * 4];
            float4 y1 = *(const float4*)&Bs[cur][kk][tx * 4 + 64];
            ull bb[8];
            bb[0] = pack2(y0.x, y0.x);
            bb[1] = pack2(y0.y, y0.y);
            bb[2] = pack2(y0.z, y0.z);
            bb[3] = pack2(y0.w, y0.w);
            bb[4] = pack2(y1.x, y1.x);
            bb[5] = pack2(y1.y, y1.y);
            bb[6] = pack2(y1.z, y1.z);
            bb[7] = pack2(y1.w, y1.w);
#pragma unroll
            for (int ip = 0; ip < 4; ++ip)
#pragma unroll
                for (int j = 0; j < 8; ++j)
                    ffma2(acc2[ip][j], aa[ip], bb[j]);
        }
        CP_WAIT0();
        __syncthreads();
        cur ^= 1;
    }

    // unpack to scalar acc[i][j]
    float acc[8][8];
#pragma unroll
    for (int ip = 0; ip < 4; ++ip)
#pragma unroll
        for (int j = 0; j < 8; ++j) {
            float2 f = unpack2(acc2[ip][j]);
            acc[2 * ip + 0][j] = f.x;
            acc[2 * ip + 1][j] = f.y;
        }

    if (MODE == 0) {
#pragma unroll
        for (int j = 0; j < 8; ++j) {
            int m = n0 + ((j < 4) ? (tx * 4 + j) : (64 + tx * 4 + (j - 4)));
            size_t base = ((size_t)b * MPTS + m) * CCH + o0 + ty * 4;
            *(float4*)&g_zT[base]      = make_float4(acc[0][j], acc[1][j], acc[2][j], acc[3][j]);
            *(float4*)&g_zT[base + 64] = make_float4(acc[4][j], acc[5][j], acc[6][j], acc[7][j]);
        }
        return;
    }

    if (MODE == 1) {
#pragma unroll
        for (int j = 0; j < 8; ++j) {
            int n = n0 + ((j < 4) ? (tx * 4 + j) : (64 + tx * 4 + (j - 4)));
            size_t wb = ((size_t)b * NPTS + n) * 4;
            float4 w4 = *(const float4*)&g_w[wb];
            int4   i4 = *(const int4*)&g_idx[wb];
            float wk[3] = {w4.x, w4.y, w4.z};
            int   ik[3] = {i4.x, i4.y, i4.z};
#pragma unroll
            for (int t = 0; t < 3; ++t) {
                const float* zp = &g_zT[((size_t)b * MPTS + ik[t]) * CCH + o0 + ty * 4];
                float4 z0 = *(const float4*)zp;
                float4 z1 = *(const float4*)(zp + 64);
                acc[0][j] += wk[t] * z0.x;
                acc[1][j] += wk[t] * z0.y;
                acc[2][j] += wk[t] * z0.z;
                acc[3][j] += wk[t] * z0.w;
                acc[4][j] += wk[t] * z1.x;
                acc[5][j] += wk[t] * z1.y;
                acc[6][j] += wk[t] * z1.z;
                acc[7][j] += wk[t] * z1.w;
            }
        }
    }

#pragma unroll
    for (int i = 0; i < 8; ++i) {
        int o = o0 + ((i < 4) ? (ty * 4 + i) : (64 + ty * 4 + (i - 4)));
        float bv = bias[o];
        float4 v0, v1;
        v0.x = fmaxf(acc[i][0] + bv, 0.0f);
        v0.y = fmaxf(acc[i][1] + bv, 0.0f);
        v0.z = fmaxf(acc[i][2] + bv, 0.0f);
        v0.w = fmaxf(acc[i][3] + bv, 0.0f);
        v1.x = fmaxf(acc[i][4] + bv, 0.0f);
        v1.y = fmaxf(acc[i][5] + bv, 0.0f);
        v1.z = fmaxf(acc[i][6] + bv, 0.0f);
        v1.w = fmaxf(acc[i][7] + bv, 0.0f);
        size_t base = (size_t)o * ldn + n0 + tx * 4;
        *(float4*)&Op[base]      = v0;
        *(float4*)&Op[base + 64] = v1;
    }
}

// ---------------------------------------------------------------------------
// Fused launch: blocks [0,128) do kNN (2 queries/thread), [128,384) zGEMM.
// ---------------------------------------------------------------------------
__global__ void __launch_bounds__(256, 2) fused0_kernel(
    const float* __restrict__ p1, const float* __restrict__ p2,
    const float* __restrict__ f2)
{
    int bx = blockIdx.x;
    if (bx < (NPTS / 512) * BB) {              // 128 kNN blocks
        knn_body(p1, p2, bx & 31, bx >> 5);
    } else {
        int i  = bx - (NPTS / 512) * BB;       // 0..255
        int nt = i & (MPTS / 128 - 1);
        int r  = i >> 5;
        int ot = r & 1;
        int b  = r >> 1;
        gemm_body<0>(g_WT1b, f2 + (size_t)b * CCH * MPTS, MPTS, CCH,
                     nullptr, nullptr, 0, nt * 128, ot * 128, b);
    }
}

__global__ void __launch_bounds__(256, 2) gemm1_kernel(
    const float* __restrict__ f1, const float* __restrict__ b1)
{
    int b = blockIdx.z;
    gemm_body<1>(g_WT1a, f1 + (size_t)b * CCH * NPTS, NPTS, CCH, b1,
                 g_y1 + (size_t)b * CCH * NPTS, NPTS,
                 blockIdx.x * 128, blockIdx.y * 128, b);
}

__global__ void __launch_bounds__(256, 2) gemm2_kernel(
    const float* __restrict__ b2, float* __restrict__ out)
{
    int b = blockIdx.z;
    gemm_body<2>(g_WT2, g_y1 + (size_t)b * CCH * NPTS, NPTS, CCH, b2,
                 out + (size_t)b * CCH * NPTS, NPTS,
                 blockIdx.x * 128, blockIdx.y * 128, b);
}

// ---------------------------------------------------------------------------
extern "C" void kernel_launch(void* const* d_in, const int* in_sizes, int n_in,
                              void* d_out, int out_size)
{
    const float* p1 = (const float*)d_in[0];
    const float* f1 = (const float*)d_in[1];
    const float* p2 = (const float*)d_in[2];
    const float* f2 = (const float*)d_in[3];
    const float* W1 = (const float*)d_in[4];
    const float* b1 = (const float*)d_in[5];
    const float* W2 = (const float*)d_in[6];
    const float* b2 = (const float*)d_in[7];
    float* out = (float*)d_out;

    const int GEMM_SMEM  = 2 * (2 * 32 * 128) * (int)sizeof(float); // 65536
    const int FUSED_SMEM = MPTS * 4 * (int)sizeof(float);           // 65536

    cudaFuncSetAttribute(fused0_kernel, cudaFuncAttributeMaxDynamicSharedMemorySize, FUSED_SMEM);
    cudaFuncSetAttribute(gemm1_kernel,  cudaFuncAttributeMaxDynamicSharedMemorySize, GEMM_SMEM);
    cudaFuncSetAttribute(gemm2_kernel,  cudaFuncAttributeMaxDynamicSharedMemorySize, GEMM_SMEM);

    // 0) transpose weights into [k][o] layout
    transpose_w_kernel<<<CCH, CCH>>>(W1, W2);

    // 1) kNN (128 blocks) + zGEMM (256 blocks) fused
    fused0_kernel<<<384, 256, FUSED_SMEM>>>(p1, p2, f2);

    // 2) y1 = relu(W1[:, 0:C] @ f1 + gather(zT) + b1)
    gemm1_kernel<<<dim3(NPTS / 128, CCH / 128, BB), 256, GEMM_SMEM>>>(f1, b1);

    // 3) out = relu(W2 @ y1 + b2)
    gemm2_kernel<<<dim3(NPTS / 128, CCH / 128, BB), 256, GEMM_SMEM>>>(b2, out);
}

// round 12
// speedup vs baseline: 1.1456x; 1.1456x over previous
#include <cuda_runtime.h>

// Problem constants
#define BB   4
#define NPTS 16384
#define MPTS 4096
#define CCH  256

typedef unsigned long long ull;

// Scratch (device globals; no allocation allowed)
__device__ float g_zT[(size_t)BB * MPTS * CCH];   // [b][m][o]
__device__ float g_y1[(size_t)BB * CCH * NPTS];   // [b][o][n]
__device__ float g_w [(size_t)BB * NPTS * 4];
__device__ int   g_idx[(size_t)BB * NPTS * 4];
__device__ float g_WT1a[CCH * CCH];               // W1[:,0:C]   transposed -> [k][o]
__device__ float g_WT1b[CCH * CCH];               // W1[:,C:2C]  transposed -> [k][o]
__device__ float g_WT2 [CCH * CCH];               // W2          transposed -> [k][o]

__device__ __forceinline__ void cp_async16(void* smem_dst, const void* gmem_src) {
    unsigned s = (unsigned)__cvta_generic_to_shared(smem_dst);
    asm volatile("cp.async.cg.shared.global [%0], [%1], 16;\n" :: "r"(s), "l"(gmem_src));
}
#define CP_COMMIT() asm volatile("cp.async.commit_group;\n" ::: "memory")
#define CP_WAIT0()  asm volatile("cp.async.wait_group 0;\n" ::: "memory")

// ---- packed f32x2 helpers ----
__device__ __forceinline__ void ffma2(ull& c, ull a, ull b) {
    asm("fma.rn.f32x2 %0, %1, %2, %0;" : "+l"(c) : "l"(a), "l"(b));
}
__device__ __forceinline__ ull fma2v(ull a, ull b, ull c) {
    ull r; asm("fma.rn.f32x2 %0, %1, %2, %3;" : "=l"(r) : "l"(a), "l"(b), "l"(c)); return r;
}
__device__ __forceinline__ ull pack2(float lo, float hi) {
    ull r;
    asm("mov.b64 %0, {%1, %2};" : "=l"(r) : "f"(lo), "f"(hi));
    return r;
}
__device__ __forceinline__ float2 unpack2(ull v) {
    float lo, hi;
    asm("mov.b64 {%0, %1}, %2;" : "=f"(lo), "=f"(hi) : "l"(v));
    return make_float2(lo, hi);
}
__device__ __forceinline__ void lds_v2u64(ull& a, ull& b, unsigned addr) {
    asm volatile("ld.shared.v2.u64 {%0, %1}, [%2];" : "=l"(a), "=l"(b) : "r"(addr));
}

extern __shared__ float sm_f[];

// ---------------------------------------------------------------------------
// Weight transpose (runs once per launch, trivial cost).
// ---------------------------------------------------------------------------
__global__ void __launch_bounds__(256) transpose_w_kernel(
    const float* __restrict__ W1, const float* __restrict__ W2)
{
    int k = blockIdx.x;
    int o = threadIdx.x;
    g_WT1a[k * CCH + o] = W1[(size_t)o * (2 * CCH) + k];
    g_WT1b[k * CCH + o] = W1[(size_t)o * (2 * CCH) + CCH + k];
    g_WT2 [k * CCH + o] = W2[(size_t)o * CCH + k];
}

// ---------------------------------------------------------------------------
// kNN. Selection bit-exact vs the XLA reference. ONE query per thread
// (256 blocks — R10's proven scheduling shape) with the verified-safe
// fast-gate machinery from R11:
//   smem pair-interleaved [x0,x1,y0,y1,z0,z1,nh0,nh1], nh = -s2/2 (exact);
//   gate: e = dot - s2/2 (approx, contraction OK) vs t = 0.5*(s1-d2) - 1e-3
//   (margin 30x the contraction error -> can never miss a true insert).
// On gate hit: VERIFIED bit-exact scalar __f*_rn recompute + insert chain
// (s2 = nh * -2 is exact).
// ---------------------------------------------------------------------------
struct Top3 { float d0, d1, d2; int i0, i1, i2; float t, s1; };

__device__ __forceinline__ void exact_insert4(Top3& s, int m,
                                              const float* sm, float px, float py, float pz)
{
#pragma unroll
    for (int u = 0; u < 4; ++u) {
        int idx = m + u;
        int base = (idx >> 1) * 8 + (idx & 1);
        float x  = sm[base + 0];
        float y  = sm[base + 2];
        float z  = sm[base + 4];
        float nh = sm[base + 6];
        float s2 = __fmul_rn(nh, -2.0f);                     // exact
        float dot = __fadd_rn(__fadd_rn(__fmul_rn(px, x),
                                        __fmul_rn(py, y)),
                              __fmul_rn(pz, z));
        float d = __fadd_rn(s.s1, s2);
        d = __fsub_rn(d, __fmul_rn(2.0f, dot));
        d = fmaxf(d, 0.0f);
        if (d < s.d2) {
            if (d < s.d1) {
                if (d < s.d0) { s.d2 = s.d1; s.i2 = s.i1; s.d1 = s.d0; s.i1 = s.i0; s.d0 = d; s.i0 = idx; }
                else          { s.d2 = s.d1; s.i2 = s.i1; s.d1 = d;  s.i1 = idx; }
            } else            { s.d2 = d;  s.i2 = idx; }
        }
    }
    s.t = 0.5f * (s.s1 - s.d2) - 1e-3f;   // gate threshold (approx-side only)
}

__device__ __forceinline__ void knn_store(const Top3& s, int b, int n)
{
    float r0 = __fdiv_rn(1.0f, __fadd_rn(s.d0, 1e-8f));
    float r1 = __fdiv_rn(1.0f, __fadd_rn(s.d1, 1e-8f));
    float r2 = __fdiv_rn(1.0f, __fadd_rn(s.d2, 1e-8f));
    float sum = __fadd_rn(__fadd_rn(r0, r1), r2);
    size_t base = ((size_t)b * NPTS + n) * 4;
    g_w[base + 0] = __fdiv_rn(r0, sum);
    g_w[base + 1] = __fdiv_rn(r1, sum);
    g_w[base + 2] = __fdiv_rn(r2, sum);
    g_w[base + 3] = 0.f;
    g_idx[base + 0] = s.i0; g_idx[base + 1] = s.i1; g_idx[base + 2] = s.i2; g_idx[base + 3] = 0;
}

__device__ __forceinline__ void knn_body(const float* __restrict__ p1,
                                         const float* __restrict__ p2,
                                         int tile, int b)
{
    // fill pair-interleaved smem
    const float* P2 = p2 + (size_t)b * MPTS * 3;
    for (int i = threadIdx.x; i < MPTS; i += 256) {
        float x = P2[i * 3 + 0];
        float y = P2[i * 3 + 1];
        float z = P2[i * 3 + 2];
        float s2 = __fadd_rn(__fadd_rn(__fmul_rn(x, x), __fmul_rn(y, y)),
                             __fmul_rn(z, z));
        int base = (i >> 1) * 8 + (i & 1);
        sm_f[base + 0] = x;
        sm_f[base + 2] = y;
        sm_f[base + 4] = z;
        sm_f[base + 6] = __fmul_rn(s2, -0.5f);               // exact
    }
    __syncthreads();

    unsigned sbase = (unsigned)__cvta_generic_to_shared(sm_f);

    int n = tile * 256 + threadIdx.x;
    const float* q = p1 + ((size_t)b * NPTS + n) * 3;
    float px = q[0], py = q[1], pz = q[2];

    Top3 A;
    A.d0 = A.d1 = A.d2 = 3.4e38f; A.i0 = A.i1 = A.i2 = 0;
    A.s1 = __fadd_rn(__fadd_rn(__fmul_rn(px, px), __fmul_rn(py, py)),
                     __fmul_rn(pz, pz));
    A.t = -3.4e38f;

    ull qx2 = pack2(px, px), qy2 = pack2(py, py), qz2 = pack2(pz, pz);

    for (int m = 0; m < MPTS; m += 4) {
        unsigned addr = sbase + (m >> 1) * 32;
        ull xy0a, xy0b, znh0a, znh0b;            // pair 0: (x0,x1),(y0,y1),(z0,z1),(nh0,nh1)
        ull xy1a, xy1b, znh1a, znh1b;            // pair 1
        lds_v2u64(xy0a, xy0b, addr);
        lds_v2u64(znh0a, znh0b, addr + 16);
        lds_v2u64(xy1a, xy1b, addr + 32);
        lds_v2u64(znh1a, znh1b, addr + 48);

        // e = px*x + py*y + pz*z + nh   (approx, contraction OK)
        ull e0 = fma2v(qx2, xy0a, fma2v(qy2, xy0b, fma2v(qz2, znh0a, znh0b)));
        ull e1 = fma2v(qx2, xy1a, fma2v(qy2, xy1b, fma2v(qz2, znh1a, znh1b)));
        float2 f0 = unpack2(e0), f1 = unpack2(e1);
        float em = fmaxf(fmaxf(f0.x, f0.y), fmaxf(f1.x, f1.y));
        if (em > A.t) exact_insert4(A, m, sm_f, px, py, pz);
    }

    knn_store(A, b, n);
}

// ---------------------------------------------------------------------------
// SGEMM 128x128, kTile=32, double-buffered cp.async both operands.
// fma.rn.f32x2 inner loop; per-element accumulation order identical to the
// verified scalar kernel (per-lane rn rounding) -> bit-identical output.
// ---------------------------------------------------------------------------
template <int MODE>
__device__ __forceinline__ void gemm_body(
    const float* __restrict__ AT,          // [K][CCH] transposed weights
    const float* __restrict__ Bp, int ldb, int K,
    const float* __restrict__ bias,
    float* __restrict__ Op, int ldn,
    int n0, int o0, int b)
{
    float (*As)[32][128] = (float(*)[32][128])sm_f;                 // 32KB
    float (*Bs)[32][128] = (float(*)[32][128])(sm_f + 2 * 32 * 128);

    int tid = threadIdx.x;
    int tx = tid & 15;
    int ty = tid >> 4;

    int ck[4], cc[4];
#pragma unroll
    for (int i = 0; i < 4; ++i) {
        int f = tid + 256 * i;
        ck[i] = f >> 5;
        cc[i] = (f & 31) * 4;
    }

    ull acc2[4][8];
#pragma unroll
    for (int i = 0; i < 4; ++i)
#pragma unroll
        for (int j = 0; j < 8; ++j) acc2[i][j] = 0ull;

    // prologue: stage 0
#pragma unroll
    for (int i = 0; i < 4; ++i) {
        cp_async16(&As[0][ck[i]][cc[i]], AT + (size_t)ck[i] * CCH + o0 + cc[i]);
        cp_async16(&Bs[0][ck[i]][cc[i]], Bp + (size_t)ck[i] * ldb + n0 + cc[i]);
    }
    CP_COMMIT();
    CP_WAIT0();
    __syncthreads();

    int cur = 0;
    for (int k0 = 0; k0 < K; k0 += 32) {
        bool nxt = (k0 + 32) < K;
        if (nxt) {
            int nb = cur ^ 1;
#pragma unroll
            for (int i = 0; i < 4; ++i) {
                cp_async16(&As[nb][ck[i]][cc[i]],
                           AT + (size_t)(k0 + 32 + ck[i]) * CCH + o0 + cc[i]);
                cp_async16(&Bs[nb][ck[i]][cc[i]],
                           Bp + (size_t)(k0 + 32 + ck[i]) * ldb + n0 + cc[i]);
            }
            CP_COMMIT();
        }
#pragma unroll
        for (int kk = 0; kk < 32; ++kk) {
            ull aa[4];
            aa[0] = *(const ull*)&As[cur][kk][ty * 4];          // o pair (0,1)
            aa[1] = *(const ull*)&As[cur][kk][ty * 4 + 2];      // o pair (2,3)
            aa[2] = *(const ull*)&As[cur][kk][ty * 4 + 64];     // o pair (4,5)
            aa[3] = *(const ull*)&As[cur][kk][ty * 4 + 66];     // o pair (6,7)
            float4 y0 = *(const float4*)&Bs[cur][kk][tx * 4];
            float4 y1 = *(const float4*)&Bs[cur][kk][tx * 4 + 64];
            ull bb[8];
            bb[0] = pack2(y0.x, y0.x);
            bb[1] = pack2(y0.y, y0.y);
            bb[2] = pack2(y0.z, y0.z);
            bb[3] = pack2(y0.w, y0.w);
            bb[4] = pack2(y1.x, y1.x);
            bb[5] = pack2(y1.y, y1.y);
            bb[6] = pack2(y1.z, y1.z);
            bb[7] = pack2(y1.w, y1.w);
#pragma unroll
            for (int ip = 0; ip < 4; ++ip)
#pragma unroll
                for (int j = 0; j < 8; ++j)
                    ffma2(acc2[ip][j], aa[ip], bb[j]);
        }
        CP_WAIT0();
        __syncthreads();
        cur ^= 1;
    }

    // unpack to scalar acc[i][j]
    float acc[8][8];
#pragma unroll
    for (int ip = 0; ip < 4; ++ip)
#pragma unroll
        for (int j = 0; j < 8; ++j) {
            float2 f = unpack2(acc2[ip][j]);
            acc[2 * ip + 0][j] = f.x;
            acc[2 * ip + 1][j] = f.y;
        }

    if (MODE == 0) {
#pragma unroll
        for (int j = 0; j < 8; ++j) {
            int m = n0 + ((j < 4) ? (tx * 4 + j) : (64 + tx * 4 + (j - 4)));
            size_t base = ((size_t)b * MPTS + m) * CCH + o0 + ty * 4;
            *(float4*)&g_zT[base]      = make_float4(acc[0][j], acc[1][j], acc[2][j], acc[3][j]);
            *(float4*)&g_zT[base + 64] = make_float4(acc[4][j], acc[5][j], acc[6][j], acc[7][j]);
        }
        return;
    }

    if (MODE == 1) {
#pragma unroll
        for (int j = 0; j < 8; ++j) {
            int n = n0 + ((j < 4) ? (tx * 4 + j) : (64 + tx * 4 + (j - 4)));
            size_t wb = ((size_t)b * NPTS + n) * 4;
            float4 w4 = *(const float4*)&g_w[wb];
            int4   i4 = *(const int4*)&g_idx[wb];
            float wk[3] = {w4.x, w4.y, w4.z};
            int   ik[3] = {i4.x, i4.y, i4.z};
#pragma unroll
            for (int t = 0; t < 3; ++t) {
                const float* zp = &g_zT[((size_t)b * MPTS + ik[t]) * CCH + o0 + ty * 4];
                float4 z0 = *(const float4*)zp;
                float4 z1 = *(const float4*)(zp + 64);
                acc[0][j] += wk[t] * z0.x;
                acc[1][j] += wk[t] * z0.y;
                acc[2][j] += wk[t] * z0.z;
                acc[3][j] += wk[t] * z0.w;
                acc[4][j] += wk[t] * z1.x;
                acc[5][j] += wk[t] * z1.y;
                acc[6][j] += wk[t] * z1.z;
                acc[7][j] += wk[t] * z1.w;
            }
        }
    }

#pragma unroll
    for (int i = 0; i < 8; ++i) {
        int o = o0 + ((i < 4) ? (ty * 4 + i) : (64 + ty * 4 + (i - 4)));
        float bv = bias[o];
        float4 v0, v1;
        v0.x = fmaxf(acc[i][0] + bv, 0.0f);
        v0.y = fmaxf(acc[i][1] + bv, 0.0f);
        v0.z = fmaxf(acc[i][2] + bv, 0.0f);
        v0.w = fmaxf(acc[i][3] + bv, 0.0f);
        v1.x = fmaxf(acc[i][4] + bv, 0.0f);
        v1.y = fmaxf(acc[i][5] + bv, 0.0f);
        v1.z = fmaxf(acc[i][6] + bv, 0.0f);
        v1.w = fmaxf(acc[i][7] + bv, 0.0f);
        size_t base = (size_t)o * ldn + n0 + tx * 4;
        *(float4*)&Op[base]      = v0;
        *(float4*)&Op[base + 64] = v1;
    }
}

// ---------------------------------------------------------------------------
// Fused launch: blocks [0,256) do kNN (1 query/thread), [256,512) zGEMM.
// ---------------------------------------------------------------------------
__global__ void __launch_bounds__(256, 2) fused0_kernel(
    const float* __restrict__ p1, const float* __restrict__ p2,
    const float* __restrict__ f2)
{
    int bx = blockIdx.x;
    if (bx < (NPTS / 256) * BB) {              // 256 kNN blocks
        knn_body(p1, p2, bx & 63, bx >> 6);
    } else {
        int i  = bx - (NPTS / 256) * BB;       // 0..255
        int nt = i & (MPTS / 128 - 1);
        int r  = i >> 5;
        int ot = r & 1;
        int b  = r >> 1;
        gemm_body<0>(g_WT1b, f2 + (size_t)b * CCH * MPTS, MPTS, CCH,
                     nullptr, nullptr, 0, nt * 128, ot * 128, b);
    }
}

__global__ void __launch_bounds__(256, 2) gemm1_kernel(
    const float* __restrict__ f1, const float* __restrict__ b1)
{
    int b = blockIdx.z;
    gemm_body<1>(g_WT1a, f1 + (size_t)b * CCH * NPTS, NPTS, CCH, b1,
                 g_y1 + (size_t)b * CCH * NPTS, NPTS,
                 blockIdx.x * 128, blockIdx.y * 128, b);
}

__global__ void __launch_bounds__(256, 2) gemm2_kernel(
    const float* __restrict__ b2, float* __restrict__ out)
{
    int b = blockIdx.z;
    gemm_body<2>(g_WT2, g_y1 + (size_t)b * CCH * NPTS, NPTS, CCH, b2,
                 out + (size_t)b * CCH * NPTS, NPTS,
                 blockIdx.x * 128, blockIdx.y * 128, b);
}

// ---------------------------------------------------------------------------
extern "C" void kernel_launch(void* const* d_in, const int* in_sizes, int n_in,
                              void* d_out, int out_size)
{
    const float* p1 = (const float*)d_in[0];
    const float* f1 = (const float*)d_in[1];
    const float* p2 = (const float*)d_in[2];
    const float* f2 = (const float*)d_in[3];
    const float* W1 = (const float*)d_in[4];
    const float* b1 = (const float*)d_in[5];
    const float* W2 = (const float*)d_in[6];
    const float* b2 = (const float*)d_in[7];
    float* out = (float*)d_out;

    const int GEMM_SMEM  = 2 * (2 * 32 * 128) * (int)sizeof(float); // 65536
    const int FUSED_SMEM = MPTS * 4 * (int)sizeof(float);           // 65536

    cudaFuncSetAttribute(fused0_kernel, cudaFuncAttributeMaxDynamicSharedMemorySize, FUSED_SMEM);
    cudaFuncSetAttribute(gemm1_kernel,  cudaFuncAttributeMaxDynamicSharedMemorySize, GEMM_SMEM);
    cudaFuncSetAttribute(gemm2_kernel,  cudaFuncAttributeMaxDynamicSharedMemorySize, GEMM_SMEM);

    // 0) transpose weights into [k][o] layout
    transpose_w_kernel<<<CCH, CCH>>>(W1, W2);

    // 1) kNN (256 blocks) + zGEMM (256 blocks) fused
    fused0_kernel<<<512, 256, FUSED_SMEM>>>(p1, p2, f2);

    // 2) y1 = relu(W1[:, 0:C] @ f1 + gather(zT) + b1)
    gemm1_kernel<<<dim3(NPTS / 128, CCH / 128, BB), 256, GEMM_SMEM>>>(f1, b1);

    // 3) out = relu(W2 @ y1 + b2)
    gemm2_kernel<<<dim3(NPTS / 128, CCH / 128, BB), 256, GEMM_SMEM>>>(b2, out);
}

// round 13
// speedup vs baseline: 1.2095x; 1.0558x over previous
#include <cuda_runtime.h>

// Problem constants
#define BB   4
#define NPTS 16384
#define MPTS 4096
#define CCH  256

typedef unsigned long long ull;

// Scratch (device globals; no allocation allowed)
__device__ float g_zT[(size_t)BB * MPTS * CCH];   // [b][m][o]
__device__ float g_y1[(size_t)BB * CCH * NPTS];   // [b][o][n]
__device__ float g_w [(size_t)BB * NPTS * 4];
__device__ int   g_idx[(size_t)BB * NPTS * 4];
__device__ float g_WT1a[CCH * CCH];               // W1[:,0:C]   transposed -> [k][o]
__device__ float g_WT1b[CCH * CCH];               // W1[:,C:2C]  transposed -> [k][o]
__device__ float g_WT2 [CCH * CCH];               // W2          transposed -> [k][o]

__device__ __forceinline__ void cp_async16(void* smem_dst, const void* gmem_src) {
    unsigned s = (unsigned)__cvta_generic_to_shared(smem_dst);
    asm volatile("cp.async.cg.shared.global [%0], [%1], 16;\n" :: "r"(s), "l"(gmem_src));
}
#define CP_COMMIT() asm volatile("cp.async.commit_group;\n" ::: "memory")
#define CP_WAIT0()  asm volatile("cp.async.wait_group 0;\n" ::: "memory")

// ---- packed f32x2 helpers ----
__device__ __forceinline__ void ffma2(ull& c, ull a, ull b) {
    asm("fma.rn.f32x2 %0, %1, %2, %0;" : "+l"(c) : "l"(a), "l"(b));
}
__device__ __forceinline__ ull fma2v(ull a, ull b, ull c) {
    ull r; asm("fma.rn.f32x2 %0, %1, %2, %3;" : "=l"(r) : "l"(a), "l"(b), "l"(c)); return r;
}
__device__ __forceinline__ ull pack2(float lo, float hi) {
    ull r;
    asm("mov.b64 %0, {%1, %2};" : "=l"(r) : "f"(lo), "f"(hi));
    return r;
}
__device__ __forceinline__ float2 unpack2(ull v) {
    float lo, hi;
    asm("mov.b64 {%0, %1}, %2;" : "=f"(lo), "=f"(hi) : "l"(v));
    return make_float2(lo, hi);
}
__device__ __forceinline__ void lds_v2u64(ull& a, ull& b, unsigned addr) {
    asm volatile("ld.shared.v2.u64 {%0, %1}, [%2];" : "=l"(a), "=l"(b) : "r"(addr));
}

extern __shared__ float sm_f[];

// ---------------------------------------------------------------------------
// Weight transpose (runs once per launch, trivial cost).
// ---------------------------------------------------------------------------
__global__ void __launch_bounds__(256) transpose_w_kernel(
    const float* __restrict__ W1, const float* __restrict__ W2)
{
    int k = blockIdx.x;
    int o = threadIdx.x;
    g_WT1a[k * CCH + o] = W1[(size_t)o * (2 * CCH) + k];
    g_WT1b[k * CCH + o] = W1[(size_t)o * (2 * CCH) + CCH + k];
    g_WT2 [k * CCH + o] = W2[(size_t)o * CCH + k];
}

// ---------------------------------------------------------------------------
// kNN. Selection bit-exact vs the XLA reference. ONE query per thread
// (256 blocks — R10's proven scheduling shape) with the verified-safe
// fast-gate machinery from R11:
//   smem pair-interleaved [x0,x1,y0,y1,z0,z1,nh0,nh1], nh = -s2/2 (exact);
//   gate: e = dot - s2/2 (approx, contraction OK) vs t = 0.5*(s1-d2) - 1e-3
//   (margin 30x the contraction error -> can never miss a true insert).
// On gate hit: VERIFIED bit-exact scalar __f*_rn recompute + insert chain
// (s2 = nh * -2 is exact).
// ---------------------------------------------------------------------------
struct Top3 { float d0, d1, d2; int i0, i1, i2; float t, s1; };

__device__ __forceinline__ void exact_insert4(Top3& s, int m,
                                              const float* sm, float px, float py, float pz)
{
#pragma unroll
    for (int u = 0; u < 4; ++u) {
        int idx = m + u;
        int base = (idx >> 1) * 8 + (idx & 1);
        float x  = sm[base + 0];
        float y  = sm[base + 2];
        float z  = sm[base + 4];
        float nh = sm[base + 6];
        float s2 = __fmul_rn(nh, -2.0f);                     // exact
        float dot = __fadd_rn(__fadd_rn(__fmul_rn(px, x),
                                        __fmul_rn(py, y)),
                              __fmul_rn(pz, z));
        float d = __fadd_rn(s.s1, s2);
        d = __fsub_rn(d, __fmul_rn(2.0f, dot));
        d = fmaxf(d, 0.0f);
        if (d < s.d2) {
            if (d < s.d1) {
                if (d < s.d0) { s.d2 = s.d1; s.i2 = s.i1; s.d1 = s.d0; s.i1 = s.i0; s.d0 = d; s.i0 = idx; }
                else          { s.d2 = s.d1; s.i2 = s.i1; s.d1 = d;  s.i1 = idx; }
            } else            { s.d2 = d;  s.i2 = idx; }
        }
    }
    s.t = 0.5f * (s.s1 - s.d2) - 1e-3f;   // gate threshold (approx-side only)
}

__device__ __forceinline__ void knn_store(const Top3& s, int b, int n)
{
    float r0 = __fdiv_rn(1.0f, __fadd_rn(s.d0, 1e-8f));
    float r1 = __fdiv_rn(1.0f, __fadd_rn(s.d1, 1e-8f));
    float r2 = __fdiv_rn(1.0f, __fadd_rn(s.d2, 1e-8f));
    float sum = __fadd_rn(__fadd_rn(r0, r1), r2);
    size_t base = ((size_t)b * NPTS + n) * 4;
    g_w[base + 0] = __fdiv_rn(r0, sum);
    g_w[base + 1] = __fdiv_rn(r1, sum);
    g_w[base + 2] = __fdiv_rn(r2, sum);
    g_w[base + 3] = 0.f;
    g_idx[base + 0] = s.i0; g_idx[base + 1] = s.i1; g_idx[base + 2] = s.i2; g_idx[base + 3] = 0;
}

__device__ __forceinline__ void knn_body(const float* __restrict__ p1,
                                         const float* __restrict__ p2,
                                         int tile, int b)
{
    // fill pair-interleaved smem
    const float* P2 = p2 + (size_t)b * MPTS * 3;
    for (int i = threadIdx.x; i < MPTS; i += 256) {
        float x = P2[i * 3 + 0];
        float y = P2[i * 3 + 1];
        float z = P2[i * 3 + 2];
        float s2 = __fadd_rn(__fadd_rn(__fmul_rn(x, x), __fmul_rn(y, y)),
                             __fmul_rn(z, z));
        int base = (i >> 1) * 8 + (i & 1);
        sm_f[base + 0] = x;
        sm_f[base + 2] = y;
        sm_f[base + 4] = z;
        sm_f[base + 6] = __fmul_rn(s2, -0.5f);               // exact
    }
    __syncthreads();

    unsigned sbase = (unsigned)__cvta_generic_to_shared(sm_f);

    int n = tile * 256 + threadIdx.x;
    const float* q = p1 + ((size_t)b * NPTS + n) * 3;
    float px = q[0], py = q[1], pz = q[2];

    Top3 A;
    A.d0 = A.d1 = A.d2 = 3.4e38f; A.i0 = A.i1 = A.i2 = 0;
    A.s1 = __fadd_rn(__fadd_rn(__fmul_rn(px, px), __fmul_rn(py, py)),
                     __fmul_rn(pz, pz));
    A.t = -3.4e38f;

    ull qx2 = pack2(px, px), qy2 = pack2(py, py), qz2 = pack2(pz, pz);

    for (int m = 0; m < MPTS; m += 4) {
        unsigned addr = sbase + (m >> 1) * 32;
        ull xy0a, xy0b, znh0a, znh0b;            // pair 0: (x0,x1),(y0,y1),(z0,z1),(nh0,nh1)
        ull xy1a, xy1b, znh1a, znh1b;            // pair 1
        lds_v2u64(xy0a, xy0b, addr);
        lds_v2u64(znh0a, znh0b, addr + 16);
        lds_v2u64(xy1a, xy1b, addr + 32);
        lds_v2u64(znh1a, znh1b, addr + 48);

        // e = px*x + py*y + pz*z + nh   (approx, contraction OK)
        ull e0 = fma2v(qx2, xy0a, fma2v(qy2, xy0b, fma2v(qz2, znh0a, znh0b)));
        ull e1 = fma2v(qx2, xy1a, fma2v(qy2, xy1b, fma2v(qz2, znh1a, znh1b)));
        float2 f0 = unpack2(e0), f1 = unpack2(e1);
        float em = fmaxf(fmaxf(f0.x, f0.y), fmaxf(f1.x, f1.y));
        if (em > A.t) exact_insert4(A, m, sm_f, px, py, pz);
    }

    knn_store(A, b, n);
}

// ---------------------------------------------------------------------------
// SGEMM 128x128, kTile=32, double-buffered cp.async both operands.
// fma.rn.f32x2 inner loop; per-element accumulation order identical to the
// verified scalar kernel (per-lane rn rounding) -> bit-identical output.
// ---------------------------------------------------------------------------
template <int MODE>
__device__ __forceinline__ void gemm_body(
    const float* __restrict__ AT,          // [K][CCH] transposed weights
    const float* __restrict__ Bp, int ldb, int K,
    const float* __restrict__ bias,
    float* __restrict__ Op, int ldn,
    int n0, int o0, int b)
{
    float (*As)[32][128] = (float(*)[32][128])sm_f;                 // 32KB
    float (*Bs)[32][128] = (float(*)[32][128])(sm_f + 2 * 32 * 128);

    int tid = threadIdx.x;
    int tx = tid & 15;
    int ty = tid >> 4;

    int ck[4], cc[4];
#pragma unroll
    for (int i = 0; i < 4; ++i) {
        int f = tid + 256 * i;
        ck[i] = f >> 5;
        cc[i] = (f & 31) * 4;
    }

    ull acc2[4][8];
#pragma unroll
    for (int i = 0; i < 4; ++i)
#pragma unroll
        for (int j = 0; j < 8; ++j) acc2[i][j] = 0ull;

    // prologue: stage 0
#pragma unroll
    for (int i = 0; i < 4; ++i) {
        cp_async16(&As[0][ck[i]][cc[i]], AT + (size_t)ck[i] * CCH + o0 + cc[i]);
        cp_async16(&Bs[0][ck[i]][cc[i]], Bp + (size_t)ck[i] * ldb + n0 + cc[i]);
    }
    CP_COMMIT();
    CP_WAIT0();
    __syncthreads();

    int cur = 0;
    for (int k0 = 0; k0 < K; k0 += 32) {
        bool nxt = (k0 + 32) < K;
        if (nxt) {
            int nb = cur ^ 1;
#pragma unroll
            for (int i = 0; i < 4; ++i) {
                cp_async16(&As[nb][ck[i]][cc[i]],
                           AT + (size_t)(k0 + 32 + ck[i]) * CCH + o0 + cc[i]);
                cp_async16(&Bs[nb][ck[i]][cc[i]],
                           Bp + (size_t)(k0 + 32 + ck[i]) * ldb + n0 + cc[i]);
            }
            CP_COMMIT();
        }
#pragma unroll
        for (int kk = 0; kk < 32; ++kk) {
            ull aa[4];
            aa[0] = *(const ull*)&As[cur][kk][ty * 4];          // o pair (0,1)
            aa[1] = *(const ull*)&As[cur][kk][ty * 4 + 2];      // o pair (2,3)
            aa[2] = *(const ull*)&As[cur][kk][ty * 4 + 64];     // o pair (4,5)
            aa[3] = *(const ull*)&As[cur][kk][ty * 4 + 66];     // o pair (6,7)
            float4 y0 = *(const float4*)&Bs[cur][kk][tx * 4];
            float4 y1 = *(const float4*)&Bs[cur][kk][tx * 4 + 64];
            ull bb[8];
            bb[0] = pack2(y0.x, y0.x);
            bb[1] = pack2(y0.y, y0.y);
            bb[2] = pack2(y0.z, y0.z);
            bb[3] = pack2(y0.w, y0.w);
            bb[4] = pack2(y1.x, y1.x);
            bb[5] = pack2(y1.y, y1.y);
            bb[6] = pack2(y1.z, y1.z);
            bb[7] = pack2(y1.w, y1.w);
#pragma unroll
            for (int ip = 0; ip < 4; ++ip)
#pragma unroll
                for (int j = 0; j < 8; ++j)
                    ffma2(acc2[ip][j], aa[ip], bb[j]);
        }
        CP_WAIT0();
        __syncthreads();
        cur ^= 1;
    }

    // unpack to scalar acc[i][j]
    float acc[8][8];
#pragma unroll
    for (int ip = 0; ip < 4; ++ip)
#pragma unroll
        for (int j = 0; j < 8; ++j) {
            float2 f = unpack2(acc2[ip][j]);
            acc[2 * ip + 0][j] = f.x;
            acc[2 * ip + 1][j] = f.y;
        }

    if (MODE == 0) {
#pragma unroll
        for (int j = 0; j < 8; ++j) {
            int m = n0 + ((j < 4) ? (tx * 4 + j) : (64 + tx * 4 + (j - 4)));
            size_t base = ((size_t)b * MPTS + m) * CCH + o0 + ty * 4;
            *(float4*)&g_zT[base]      = make_float4(acc[0][j], acc[1][j], acc[2][j], acc[3][j]);
            *(float4*)&g_zT[base + 64] = make_float4(acc[4][j], acc[5][j], acc[6][j], acc[7][j]);
        }
        return;
    }

    if (MODE == 1) {
#pragma unroll
        for (int j = 0; j < 8; ++j) {
            int n = n0 + ((j < 4) ? (tx * 4 + j) : (64 + tx * 4 + (j - 4)));
            size_t wb = ((size_t)b * NPTS + n) * 4;
            float4 w4 = *(const float4*)&g_w[wb];
            int4   i4 = *(const int4*)&g_idx[wb];
            float wk[3] = {w4.x, w4.y, w4.z};
            int   ik[3] = {i4.x, i4.y, i4.z};
#pragma unroll
            for (int t = 0; t < 3; ++t) {
                const float* zp = &g_zT[((size_t)b * MPTS + ik[t]) * CCH + o0 + ty * 4];
                float4 z0 = *(const float4*)zp;
                float4 z1 = *(const float4*)(zp + 64);
                acc[0][j] += wk[t] * z0.x;
                acc[1][j] += wk[t] * z0.y;
                acc[2][j] += wk[t] * z0.z;
                acc[3][j] += wk[t] * z0.w;
                acc[4][j] += wk[t] * z1.x;
                acc[5][j] += wk[t] * z1.y;
                acc[6][j] += wk[t] * z1.z;
                acc[7][j] += wk[t] * z1.w;
            }
        }
    }

#pragma unroll
    for (int i = 0; i < 8; ++i) {
        int o = o0 + ((i < 4) ? (ty * 4 + i) : (64 + ty * 4 + (i - 4)));
        float bv = bias[o];
        float4 v0, v1;
        v0.x = fmaxf(acc[i][0] + bv, 0.0f);
        v0.y = fmaxf(acc[i][1] + bv, 0.0f);
        v0.z = fmaxf(acc[i][2] + bv, 0.0f);
        v0.w = fmaxf(acc[i][3] + bv, 0.0f);
        v1.x = fmaxf(acc[i][4] + bv, 0.0f);
        v1.y = fmaxf(acc[i][5] + bv, 0.0f);
        v1.z = fmaxf(acc[i][6] + bv, 0.0f);
        v1.w = fmaxf(acc[i][7] + bv, 0.0f);
        size_t base = (size_t)o * ldn + n0 + tx * 4;
        *(float4*)&Op[base]      = v0;
        *(float4*)&Op[base + 64] = v1;
    }
}

// ---------------------------------------------------------------------------
// Fused launch: blocks [0,256) do kNN (1 query/thread), [256,512) zGEMM.
// ---------------------------------------------------------------------------
__global__ void __launch_bounds__(256, 2) fused0_kernel(
    const float* __restrict__ p1, const float* __restrict__ p2,
    const float* __restrict__ f2)
{
    int bx = blockIdx.x;
    if (bx < (NPTS / 256) * BB) {              // 256 kNN blocks
        knn_body(p1, p2, bx & 63, bx >> 6);
    } else {
        int i  = bx - (NPTS / 256) * BB;       // 0..255
        int nt = i & (MPTS / 128 - 1);
        int r  = i >> 5;
        int ot = r & 1;
        int b  = r >> 1;
        gemm_body<0>(g_WT1b, f2 + (size_t)b * CCH * MPTS, MPTS, CCH,
                     nullptr, nullptr, 0, nt * 128, ot * 128, b);
    }
}

__global__ void __launch_bounds__(256, 2) gemm1_kernel(
    const float* __restrict__ f1, const float* __restrict__ b1)
{
    int b = blockIdx.z;
    gemm_body<1>(g_WT1a, f1 + (size_t)b * CCH * NPTS, NPTS, CCH, b1,
                 g_y1 + (size_t)b * CCH * NPTS, NPTS,
                 blockIdx.x * 128, blockIdx.y * 128, b);
}

__global__ void __launch_bounds__(256, 2) gemm2_kernel(
    const float* __restrict__ b2, float* __restrict__ out)
{
    int b = blockIdx.z;
    gemm_body<2>(g_WT2, g_y1 + (size_t)b * CCH * NPTS, NPTS, CCH, b2,
                 out + (size_t)b * CCH * NPTS, NPTS,
                 blockIdx.x * 128, blockIdx.y * 128, b);
}

// ---------------------------------------------------------------------------
extern "C" void kernel_launch(void* const* d_in, const int* in_sizes, int n_in,
                              void* d_out, int out_size)
{
    const float* p1 = (const float*)d_in[0];
    const float* f1 = (const float*)d_in[1];
    const float* p2 = (const float*)d_in[2];
    const float* f2 = (const float*)d_in[3];
    const float* W1 = (const float*)d_in[4];
    const float* b1 = (const float*)d_in[5];
    const float* W2 = (const float*)d_in[6];
    const float* b2 = (const float*)d_in[7];
    float* out = (float*)d_out;

    const int GEMM_SMEM  = 2 * (2 * 32 * 128) * (int)sizeof(float); // 65536
    const int FUSED_SMEM = MPTS * 4 * (int)sizeof(float);           // 65536

    cudaFuncSetAttribute(fused0_kernel, cudaFuncAttributeMaxDynamicSharedMemorySize, FUSED_SMEM);
    cudaFuncSetAttribute(gemm1_kernel,  cudaFuncAttributeMaxDynamicSharedMemorySize, GEMM_SMEM);
    cudaFuncSetAttribute(gemm2_kernel,  cudaFuncAttributeMaxDynamicSharedMemorySize, GEMM_SMEM);

    // 0) transpose weights into [k][o] layout
    transpose_w_kernel<<<CCH, CCH>>>(W1, W2);

    // 1) kNN (256 blocks) + zGEMM (256 blocks) fused
    fused0_kernel<<<512, 256, FUSED_SMEM>>>(p1, p2, f2);

    // 2) y1 = relu(W1[:, 0:C] @ f1 + gather(zT) + b1)
    gemm1_kernel<<<dim3(NPTS / 128, CCH / 128, BB), 256, GEMM_SMEM>>>(f1, b1);

    // 3) out = relu(W2 @ y1 + b2)
    gemm2_kernel<<<dim3(NPTS / 128, CCH / 128, BB), 256, GEMM_SMEM>>>(b2, out);
}